// round 13
// baseline (speedup 1.0000x reference)
#include <cuda_runtime.h>
#include <math.h>

#define NN 50000
#define NE 800000
#define ET 850000      /* NE + NN self loops */
#define FD 128
#define NG 256
#define BN_EPS 1e-5f
#define NEG 0.2f

// ---------------- device scratch (static, no allocation) ----------------
__device__ float g_h[NN*FD];      // current node features
__device__ float g_h2[NN*FD];     // W-transformed features
__device__ float g_stat[2*FD];    // BN sum / sumsq
__device__ float g_Wf[FD*FD];     // BN-folded weight (fp32)
__device__ float g_bf[FD];        // BN-folded bias
__device__ float g_als[NN*4];
__device__ float g_ald[NN*4];
__device__ int   g_deg[NN];
__device__ int   g_off[NN+1];
__device__ int   g_cur[NN];
__device__ int   g_csrc[ET];      // CSR source node per slot (sorted by dst)
__device__ float g_pool[NG*FD];
__device__ float g_g2[NG*FD];
__device__ float g_sc1[FD], g_sh1[FD], g_sc2[FD], g_sh2[FD];

// ---------------- helpers ----------------
__device__ __forceinline__ void red_add_v4(float* p, float4 v) {
    asm volatile("red.global.add.v4.f32 [%0], {%1,%2,%3,%4};"
                 :: "l"(p), "f"(v.x), "f"(v.y), "f"(v.z), "f"(v.w) : "memory");
}

// pack two floats as bf16x2: lo -> bits[15:0], hi -> bits[31:16]
__device__ __forceinline__ unsigned pack_bf16x2(float lo, float hi) {
    unsigned r;
    asm("cvt.rn.bf16x2.f32 %0, %1, %2;" : "=r"(r) : "f"(hi), "f"(lo));
    return r;
}
__device__ __forceinline__ float bf16lo_f(unsigned p) { return __uint_as_float(p << 16); }
__device__ __forceinline__ float bf16hi_f(unsigned p) { return __uint_as_float(p & 0xffff0000u); }

#define MMA_BF16(c, a0,a1,a2,a3, b0,b1) \
    asm volatile("mma.sync.aligned.m16n8k16.row.col.f32.bf16.bf16.f32 " \
        "{%0,%1,%2,%3}, {%4,%5,%6,%7}, {%8,%9}, {%0,%1,%2,%3};" \
        : "+f"(c[0]), "+f"(c[1]), "+f"(c[2]), "+f"(c[3]) \
        : "r"(a0), "r"(a1), "r"(a2), "r"(a3), "r"(b0), "r"(b1))

// ---------------- CSR build (edges fixed across the 3 convs) --------------
__global__ void zero_deg() {
    int t = blockIdx.x*blockDim.x + threadIdx.x;
    if (t < NN) g_deg[t] = 0;
}

__global__ void count_deg(const int* __restrict__ dst) {
    int e = blockIdx.x*blockDim.x + threadIdx.x;
    if (e >= ET) return;
    int d = (e < NE) ? dst[e] : (e - NE);
    atomicAdd(&g_deg[d], 1);
}

__global__ void scan_deg() {          // 1 block, 1024 threads
    const int C = (NN + 1023) / 1024;
    int tid = threadIdx.x;
    int start = tid * C;
    int end = min(start + C, NN);
    int s = 0;
    for (int i = start; i < end; i++) s += g_deg[i];
    __shared__ int wsum[32];
    int lane = tid & 31, wid = tid >> 5;
    int v = s;
    #pragma unroll
    for (int off = 1; off < 32; off <<= 1) {
        int t = __shfl_up_sync(0xffffffffu, v, off);
        if (lane >= off) v += t;
    }
    if (lane == 31) wsum[wid] = v;
    __syncthreads();
    if (wid == 0) {
        int w = wsum[lane];
        #pragma unroll
        for (int off = 1; off < 32; off <<= 1) {
            int t = __shfl_up_sync(0xffffffffu, w, off);
            if (lane >= off) w += t;
        }
        wsum[lane] = w;
    }
    __syncthreads();
    int excl = v - s + ((wid > 0) ? wsum[wid-1] : 0);
    int run = excl;
    for (int i = start; i < end; i++) {
        g_off[i] = run;
        g_cur[i] = run;
        run += g_deg[i];
    }
    if (tid == 1023) g_off[NN] = excl;
}

__global__ void scatter_csr(const int* __restrict__ src, const int* __restrict__ dst) {
    int e = blockIdx.x*blockDim.x + threadIdx.x;
    if (e >= ET) return;
    int s = (e < NE) ? src[e] : (e - NE);
    int d = (e < NE) ? dst[e] : (e - NE);
    int pos = atomicAdd(&g_cur[d], 1);
    g_csrc[pos] = s;
}

// ---------------- BN stats + fold ----------------
__global__ void zero_stat() { g_stat[threadIdx.x] = 0.f; }

__global__ void bn_stats(const float* __restrict__ X, int n) {
    int j = threadIdx.x;
    float s = 0.f, q = 0.f;
    for (int r = blockIdx.x; r < n; r += gridDim.x) {
        float v = X[r*FD + j];
        s += v; q += v*v;
    }
    atomicAdd(&g_stat[j], s);
    atomicAdd(&g_stat[FD + j], q);
}

__global__ void fold(const float* __restrict__ W, const float* __restrict__ gamma,
                     const float* __restrict__ beta, float invN) {
    __shared__ float sc[FD], sh[FD];
    int j = threadIdx.x;
    float m   = g_stat[j] * invN;
    float var = g_stat[FD + j] * invN - m*m;
    float scale = gamma[j] * rsqrtf(var + BN_EPS);
    sc[j] = scale;
    sh[j] = beta[j] - m * scale;
    __syncthreads();
    float b = 0.f;
    for (int k = 0; k < FD; k++) {
        float w = W[k*FD + j];
        g_Wf[k*FD + j] = sc[k] * w;
        b += sh[k] * w;
    }
    g_bf[j] = b;
}

// -------- tensor-core GEMM (bf16x3 split): C = A @ g_Wf + g_bf (opt relu) --
// CTA: 256 threads = 8 warps = 4 m-tiles(16 rows) x 2 n-halves(64 cols).
// smem: As hi/lo [64][68] u32 (bf16 pairs along k), Bs hi/lo [64][136] u32.
#define AS_STRIDE 68
#define BS_STRIDE 136
#define GEMM_SMEM ((2*64*AS_STRIDE + 2*64*BS_STRIDE)*4)

__global__ void gemm128_mma(const float* __restrict__ A, float* __restrict__ C,
                            int M, int relu) {
    extern __shared__ unsigned smu[];
    unsigned* As_hi = smu;
    unsigned* As_lo = As_hi + 64*AS_STRIDE;
    unsigned* Bs_hi = As_lo + 64*AS_STRIDE;
    unsigned* Bs_lo = Bs_hi + 64*BS_STRIDE;
    int tid = threadIdx.x;
    int row0 = blockIdx.x * 64;

    // stage W: hi/lo bf16 pairs along k (k2 = k/2)
    for (int i = tid; i < 64*128; i += 256) {
        int k2 = i >> 7, n = i & 127;
        float w0 = g_Wf[(2*k2)*FD + n];
        float w1 = g_Wf[(2*k2+1)*FD + n];
        unsigned hp = pack_bf16x2(w0, w1);
        float r0 = w0 - bf16lo_f(hp);
        float r1 = w1 - bf16hi_f(hp);
        Bs_hi[k2*BS_STRIDE + n] = hp;
        Bs_lo[k2*BS_STRIDE + n] = pack_bf16x2(r0, r1);
    }
    // stage A tile (64 rows), hi/lo bf16 pairs along k
    for (int i = tid; i < 64*64; i += 256) {
        int r = i >> 6, c2 = i & 63;
        float2 a = make_float2(0.f, 0.f);
        if (row0 + r < M) a = ((const float2*)A)[(size_t)(row0 + r)*64 + c2];
        unsigned hp = pack_bf16x2(a.x, a.y);
        float r0 = a.x - bf16lo_f(hp);
        float r1 = a.y - bf16hi_f(hp);
        As_hi[r*AS_STRIDE + c2] = hp;
        As_lo[r*AS_STRIDE + c2] = pack_bf16x2(r0, r1);
    }
    __syncthreads();

    int wid = tid >> 5, lane = tid & 31;
    int g = lane >> 2, t = lane & 3;
    int mw = wid & 3, nh = wid >> 2;
    int ra = (mw*16 + g)*AS_STRIDE;
    int rb = ra + 8*AS_STRIDE;

    float c[8][4];
    #pragma unroll
    for (int i = 0; i < 8; i++) { c[i][0]=0.f; c[i][1]=0.f; c[i][2]=0.f; c[i][3]=0.f; }

    #pragma unroll
    for (int kk = 0; kk < 8; kk++) {
        int ca = kk*8 + t;
        unsigned ah0 = As_hi[ra + ca],     ah1 = As_hi[rb + ca];
        unsigned ah2 = As_hi[ra + ca + 4], ah3 = As_hi[rb + ca + 4];
        unsigned al0 = As_lo[ra + ca],     al1 = As_lo[rb + ca];
        unsigned al2 = As_lo[ra + ca + 4], al3 = As_lo[rb + ca + 4];
        int kb0 = (kk*8 + t)*BS_STRIDE + nh*64;
        int kb1 = kb0 + 4*BS_STRIDE;
        #pragma unroll
        for (int nt = 0; nt < 8; nt++) {
            int n = nt*8 + g;
            unsigned bh0 = Bs_hi[kb0 + n], bh1 = Bs_hi[kb1 + n];
            unsigned bl0 = Bs_lo[kb0 + n], bl1 = Bs_lo[kb1 + n];
            MMA_BF16(c[nt], ah0, ah1, ah2, ah3, bh0, bh1);
            MMA_BF16(c[nt], ah0, ah1, ah2, ah3, bl0, bl1);
            MMA_BF16(c[nt], al0, al1, al2, al3, bh0, bh1);
        }
    }

    // epilogue: D[g][2t,2t+1] = c0,c1 ; D[g+8][2t,2t+1] = c2,c3
    #pragma unroll
    for (int nt = 0; nt < 8; nt++) {
        int col = nh*64 + nt*8 + 2*t;
        float b0 = g_bf[col], b1 = g_bf[col+1];
        int r = row0 + mw*16 + g;
        float v0 = c[nt][0] + b0, v1 = c[nt][1] + b1;
        float v2 = c[nt][2] + b0, v3 = c[nt][3] + b1;
        if (relu) {
            v0 = fmaxf(v0, 0.f); v1 = fmaxf(v1, 0.f);
            v2 = fmaxf(v2, 0.f); v3 = fmaxf(v3, 0.f);
        }
        if (r < M)     ((float2*)C)[((size_t)r*FD + col) >> 1]     = make_float2(v0, v1);
        if (r + 8 < M) ((float2*)C)[((size_t)(r+8)*FD + col) >> 1] = make_float2(v2, v3);
    }
}

// ---------------- per-node attention coefficients -----------
__global__ void node_al(const float* __restrict__ asrc, const float* __restrict__ adst) {
    int lane = threadIdx.x & 31;
    int warp = (blockIdx.x*blockDim.x + threadIdx.x) >> 5;
    int nwarps = (gridDim.x*blockDim.x) >> 5;
    int head = lane >> 3, dq = lane & 7;
    float4 as4 = ((const float4*)asrc)[head*8 + dq];
    float4 ad4 = ((const float4*)adst)[head*8 + dq];
    for (int n = warp; n < NN; n += nwarps) {
        float4 v = ((const float4*)g_h2)[n*32 + lane];
        float ps = v.x*as4.x + v.y*as4.y + v.z*as4.z + v.w*as4.w;
        float pd = v.x*ad4.x + v.y*ad4.y + v.z*ad4.z + v.w*ad4.w;
        #pragma unroll
        for (int off = 4; off; off >>= 1) {
            ps += __shfl_down_sync(0xffffffffu, ps, off, 8);
            pd += __shfl_down_sync(0xffffffffu, pd, off, 8);
        }
        if (dq == 0) {
            g_als[n*4 + head] = ps;
            g_ald[n*4 + head] = pd;
        }
    }
}

// ------ fused GAT aggregation: warp per node, online softmax, 2 passes ----
__global__ void gat_gather(const float* __restrict__ bias) {
    int warp = (blockIdx.x*blockDim.x + threadIdx.x) >> 5;
    if (warp >= NN) return;
    int lane = threadIdx.x & 31;
    int n = warp;
    int rs = g_off[n], re = g_off[n+1];

    float4 aldv = ((const float4*)g_ald)[n];

    // pass A: per-head online (max, sum) — lane-parallel over edges
    const float MINIT = -1e30f;   // finite: avoids inf-inf NaN on empty lanes
    float m0=MINIT, m1=MINIT, m2=MINIT, m3=MINIT;
    float s0=0.f, s1=0.f, s2=0.f, s3=0.f;
    for (int e = rs + lane; e < re; e += 32) {
        int s = g_csrc[e];
        float4 a = ((const float4*)g_als)[s];
        float l0 = a.x + aldv.x; l0 = (l0 > 0.f) ? l0 : NEG*l0;
        float l1 = a.y + aldv.y; l1 = (l1 > 0.f) ? l1 : NEG*l1;
        float l2 = a.z + aldv.z; l2 = (l2 > 0.f) ? l2 : NEG*l2;
        float l3 = a.w + aldv.w; l3 = (l3 > 0.f) ? l3 : NEG*l3;
        float nm;
        nm = fmaxf(m0, l0); s0 = s0*__expf(m0-nm) + __expf(l0-nm); m0 = nm;
        nm = fmaxf(m1, l1); s1 = s1*__expf(m1-nm) + __expf(l1-nm); m1 = nm;
        nm = fmaxf(m2, l2); s2 = s2*__expf(m2-nm) + __expf(l2-nm); m2 = nm;
        nm = fmaxf(m3, l3); s3 = s3*__expf(m3-nm) + __expf(l3-nm); m3 = nm;
    }
    #pragma unroll
    for (int off = 16; off; off >>= 1) {
        float om, os, nm;
        om = __shfl_xor_sync(0xffffffffu, m0, off); os = __shfl_xor_sync(0xffffffffu, s0, off);
        nm = fmaxf(m0, om); s0 = s0*__expf(m0-nm) + os*__expf(om-nm); m0 = nm;
        om = __shfl_xor_sync(0xffffffffu, m1, off); os = __shfl_xor_sync(0xffffffffu, s1, off);
        nm = fmaxf(m1, om); s1 = s1*__expf(m1-nm) + os*__expf(om-nm); m1 = nm;
        om = __shfl_xor_sync(0xffffffffu, m2, off); os = __shfl_xor_sync(0xffffffffu, s2, off);
        nm = fmaxf(m2, om); s2 = s2*__expf(m2-nm) + os*__expf(om-nm); m2 = nm;
        om = __shfl_xor_sync(0xffffffffu, m3, off); os = __shfl_xor_sync(0xffffffffu, s3, off);
        nm = fmaxf(m3, om); s3 = s3*__expf(m3-nm) + os*__expf(om-nm); m3 = nm;
    }

    int head = lane >> 3;
    float mh   = (head < 2) ? (head ? m1 : m0) : ((head == 2) ? m2 : m3);
    float sh   = (head < 2) ? (head ? s1 : s0) : ((head == 2) ? s2 : s3);
    float alD  = (head < 2) ? (head ? aldv.y : aldv.x) : ((head == 2) ? aldv.z : aldv.w);
    float invh = 1.f / (sh + 1e-16f);

    // pass B: weighted gather-accumulate (dim-parallel, sequential over edges)
    float4 acc = make_float4(0.f, 0.f, 0.f, 0.f);
    int e = rs;
    int s_cur = (e < re) ? g_csrc[e] : 0;
    for (; e < re; e++) {
        int s = s_cur;
        if (e + 1 < re) s_cur = g_csrc[e+1];
        float4 a = ((const float4*)g_als)[s];     // broadcast (same addr all lanes)
        float alS = (head < 2) ? (head ? a.y : a.x) : ((head == 2) ? a.z : a.w);
        float l = alS + alD; l = (l > 0.f) ? l : NEG*l;
        float w = __expf(l - mh) * invh;
        float4 v = ((const float4*)g_h2)[s*32 + lane];
        acc.x += v.x*w; acc.y += v.y*w;
        acc.z += v.z*w; acc.w += v.w*w;
    }

    float4 b4 = ((const float4*)bias)[lane];
    acc.x = fmaxf(acc.x + b4.x, 0.f); acc.y = fmaxf(acc.y + b4.y, 0.f);
    acc.z = fmaxf(acc.z + b4.z, 0.f); acc.w = fmaxf(acc.w + b4.w, 0.f);
    ((float4*)g_h)[n*32 + lane] = acc;
}

// ---------------- pooling + head ----------------
__global__ void zero_pool() {
    int t = blockIdx.x*blockDim.x + threadIdx.x;
    if (t < NG*FD) g_pool[t] = 0.f;
}

__global__ void pool_kernel(const int* __restrict__ batch) {
    int t = blockIdx.x*blockDim.x + threadIdx.x;
    if (t >= NN*32) return;
    int node = t >> 5, q = t & 31;
    int b = batch[node];
    float4 v = ((const float4*)g_h)[t];
    red_add_v4(&g_pool[b*FD + q*4], v);
}

__global__ void small_bn(int sel, const float* __restrict__ gamma,
                         const float* __restrict__ beta) {
    const float* X = sel ? g_g2 : g_pool;
    float* sc = sel ? g_sc2 : g_sc1;
    float* sh = sel ? g_sh2 : g_sh1;
    int j = threadIdx.x;
    float s = 0.f, q = 0.f;
    for (int r = 0; r < NG; r++) { float v = X[r*FD + j]; s += v; q += v*v; }
    float m = s * (1.f/NG);
    float var = q * (1.f/NG) - m*m;
    float scale = gamma[j] * rsqrtf(var + BN_EPS);
    sc[j] = scale; sh[j] = beta[j] - m*scale;
}

__global__ void small_linear(const float* __restrict__ W, const float* __restrict__ b) {
    __shared__ float row[FD];
    int r = blockIdx.x, j = threadIdx.x;
    row[j] = g_pool[r*FD + j] * g_sc1[j] + g_sh1[j];
    __syncthreads();
    float acc = b[j];
    #pragma unroll 8
    for (int k = 0; k < FD; k++) acc += row[k] * W[k*FD + j];
    g_g2[r*FD + j] = fmaxf(acc, 0.f);
}

__global__ void classifier(const float* __restrict__ W, const float* __restrict__ b,
                           float* __restrict__ out) {
    __shared__ float row[FD];
    __shared__ float z[16];
    __shared__ float red2[2];
    int r = blockIdx.x, t = threadIdx.x;
    for (int i = t; i < FD; i += 32) row[i] = g_g2[r*FD + i] * g_sc2[i] + g_sh2[i];
    __syncthreads();
    if (t < 10) {
        float acc = b[t];
        for (int k = 0; k < FD; k++) acc += row[k] * W[k*10 + t];
        z[t] = acc;
    }
    __syncthreads();
    if (t == 0) {
        float m = z[0];
        for (int i = 1; i < 10; i++) m = fmaxf(m, z[i]);
        float s = 0.f;
        for (int i = 0; i < 10; i++) s += expf(z[i] - m);
        red2[0] = m; red2[1] = logf(s);
    }
    __syncthreads();
    if (t < 10) out[r*10 + t] = z[t] - red2[0] - red2[1];
}

// ---------------- launch ----------------
extern "C" void kernel_launch(void* const* d_in, const int* in_sizes, int n_in,
                              void* d_out, int out_size) {
    const float* x        = (const float*)d_in[0];
    const int*   eidx     = (const int*)  d_in[1];
    const int*   batch    = (const int*)  d_in[2];
    const float* w_feat   = (const float*)d_in[3];
    const float* bnf_g    = (const float*)d_in[4];
    const float* bnf_b    = (const float*)d_in[5];
    const float* bnc_g    = (const float*)d_in[6];
    const float* bnc_b    = (const float*)d_in[7];
    const float* gat_w    = (const float*)d_in[8];
    const float* gat_asrc = (const float*)d_in[9];
    const float* gat_adst = (const float*)d_in[10];
    const float* gat_b    = (const float*)d_in[11];
    const float* bnfc_g   = (const float*)d_in[12];
    const float* bnfc_b   = (const float*)d_in[13];
    const float* lin_w    = (const float*)d_in[14];
    const float* lin_b    = (const float*)d_in[15];
    const float* bnh_g    = (const float*)d_in[16];
    const float* bnh_b    = (const float*)d_in[17];
    const float* cls_w    = (const float*)d_in[18];
    const float* cls_b    = (const float*)d_in[19];
    float* out = (float*)d_out;

    const int* src = eidx;
    const int* dst = eidx + NE;

    float *p_h, *p_h2;
    cudaGetSymbolAddress((void**)&p_h,  g_h);
    cudaGetSymbolAddress((void**)&p_h2, g_h2);

    cudaFuncSetAttribute(gemm128_mma, cudaFuncAttributeMaxDynamicSharedMemorySize, GEMM_SMEM);
    const int GEMM_GRID = (NN + 63) / 64;

    // ---- CSR build (reused by all 3 convs) ----
    zero_deg<<<(NN+255)/256, 256>>>();
    count_deg<<<(ET+255)/256, 256>>>(dst);
    scan_deg<<<1, 1024>>>();
    scatter_csr<<<(ET+255)/256, 256>>>(src, dst);

    // ---- bn_feat fold + gfn GCN + relu ----
    zero_stat<<<1, 256>>>();
    bn_stats<<<512, FD>>>(x, NN);
    fold<<<1, FD>>>(w_feat, bnf_g, bnf_b, 1.f/NN);
    gemm128_mma<<<GEMM_GRID, 256, GEMM_SMEM>>>(x, p_h, NN, 1);

    // ---- 3 x (BN + GATConv + relu) ----
    for (int i = 0; i < 3; i++) {
        zero_stat<<<1, 256>>>();
        bn_stats<<<512, FD>>>(p_h, NN);
        fold<<<1, FD>>>(gat_w + i*FD*FD, bnc_g + i*FD, bnc_b + i*FD, 1.f/NN);
        gemm128_mma<<<GEMM_GRID, 256, GEMM_SMEM>>>(p_h, p_h2, NN, 0);
        node_al<<<1024, 256>>>(gat_asrc + i*FD, gat_adst + i*FD);
        gat_gather<<<(NN*32+255)/256, 256>>>(gat_b + i*FD);
    }

    // ---- pool + head ----
    zero_pool<<<128, 256>>>();
    pool_kernel<<<NN*32/256, 256>>>(batch);
    small_bn<<<1, FD>>>(0, bnfc_g, bnfc_b);
    small_linear<<<NG, FD>>>(lin_w, lin_b);
    small_bn<<<1, FD>>>(1, bnh_g, bnh_b);
    classifier<<<NG, 32>>>(cls_w, cls_b, out);
}

// round 14
// speedup vs baseline: 1.0062x; 1.0062x over previous
#include <cuda_runtime.h>
#include <math.h>

#define NN 50000
#define NE 800000
#define ET 850000      /* NE + NN self loops */
#define FD 128
#define NG 256
#define BN_EPS 1e-5f
#define NEG 0.2f

// ---------------- device scratch (static, no allocation) ----------------
__device__ float g_h[NN*FD];      // current node features
__device__ float g_h2[NN*FD];     // W-transformed features
__device__ float g_stat[2*FD];    // BN sum / sumsq
__device__ float g_Wf[FD*FD];     // BN-folded weight (fp32)
__device__ float g_bf[FD];        // BN-folded bias
__device__ float g_als[NN*4];
__device__ float g_ald[NN*4];
__device__ int   g_deg[NN];
__device__ int   g_off[NN+1];
__device__ int   g_cur[NN];
__device__ int   g_csrc[ET];      // CSR source node per slot (sorted by dst)
__device__ float g_pool[NG*FD];
__device__ float g_g2[NG*FD];
__device__ float g_sc1[FD], g_sh1[FD], g_sc2[FD], g_sh2[FD];

// ---------------- helpers ----------------
__device__ __forceinline__ void red_add_v4(float* p, float4 v) {
    asm volatile("red.global.add.v4.f32 [%0], {%1,%2,%3,%4};"
                 :: "l"(p), "f"(v.x), "f"(v.y), "f"(v.z), "f"(v.w) : "memory");
}

// pack two floats as bf16x2: lo -> bits[15:0], hi -> bits[31:16]
__device__ __forceinline__ unsigned pack_bf16x2(float lo, float hi) {
    unsigned r;
    asm("cvt.rn.bf16x2.f32 %0, %1, %2;" : "=r"(r) : "f"(hi), "f"(lo));
    return r;
}
__device__ __forceinline__ float bf16lo_f(unsigned p) { return __uint_as_float(p << 16); }
__device__ __forceinline__ float bf16hi_f(unsigned p) { return __uint_as_float(p & 0xffff0000u); }

#define MMA_BF16(c, a0,a1,a2,a3, b0,b1) \
    asm volatile("mma.sync.aligned.m16n8k16.row.col.f32.bf16.bf16.f32 " \
        "{%0,%1,%2,%3}, {%4,%5,%6,%7}, {%8,%9}, {%0,%1,%2,%3};" \
        : "+f"(c[0]), "+f"(c[1]), "+f"(c[2]), "+f"(c[3]) \
        : "r"(a0), "r"(a1), "r"(a2), "r"(a3), "r"(b0), "r"(b1))

// ---------------- CSR build (edges fixed across the 3 convs) --------------
__global__ void zero_deg() {
    int t = blockIdx.x*blockDim.x + threadIdx.x;
    if (t < NN) g_deg[t] = 0;
}

__global__ void count_deg(const int* __restrict__ dst) {
    int e = blockIdx.x*blockDim.x + threadIdx.x;
    if (e >= ET) return;
    int d = (e < NE) ? dst[e] : (e - NE);
    atomicAdd(&g_deg[d], 1);
}

__global__ void scan_deg() {          // 1 block, 1024 threads
    const int C = (NN + 1023) / 1024;
    int tid = threadIdx.x;
    int start = tid * C;
    int end = min(start + C, NN);
    int s = 0;
    for (int i = start; i < end; i++) s += g_deg[i];
    __shared__ int wsum[32];
    int lane = tid & 31, wid = tid >> 5;
    int v = s;
    #pragma unroll
    for (int off = 1; off < 32; off <<= 1) {
        int t = __shfl_up_sync(0xffffffffu, v, off);
        if (lane >= off) v += t;
    }
    if (lane == 31) wsum[wid] = v;
    __syncthreads();
    if (wid == 0) {
        int w = wsum[lane];
        #pragma unroll
        for (int off = 1; off < 32; off <<= 1) {
            int t = __shfl_up_sync(0xffffffffu, w, off);
            if (lane >= off) w += t;
        }
        wsum[lane] = w;
    }
    __syncthreads();
    int excl = v - s + ((wid > 0) ? wsum[wid-1] : 0);
    int run = excl;
    for (int i = start; i < end; i++) {
        g_off[i] = run;
        g_cur[i] = run;
        run += g_deg[i];
    }
    if (tid == 1023) g_off[NN] = excl;
}

__global__ void scatter_csr(const int* __restrict__ src, const int* __restrict__ dst) {
    int e = blockIdx.x*blockDim.x + threadIdx.x;
    if (e >= ET) return;
    int s = (e < NE) ? src[e] : (e - NE);
    int d = (e < NE) ? dst[e] : (e - NE);
    int pos = atomicAdd(&g_cur[d], 1);
    g_csrc[pos] = s;
}

// ---------------- BN stats + fold ----------------
__global__ void zero_stat() { g_stat[threadIdx.x] = 0.f; }

__global__ void bn_stats(const float* __restrict__ X, int n) {
    int j = threadIdx.x;
    float s = 0.f, q = 0.f;
    for (int r = blockIdx.x; r < n; r += gridDim.x) {
        float v = X[r*FD + j];
        s += v; q += v*v;
    }
    atomicAdd(&g_stat[j], s);
    atomicAdd(&g_stat[FD + j], q);
}

__global__ void fold(const float* __restrict__ W, const float* __restrict__ gamma,
                     const float* __restrict__ beta, float invN) {
    __shared__ float sc[FD], sh[FD];
    int j = threadIdx.x;
    float m   = g_stat[j] * invN;
    float var = g_stat[FD + j] * invN - m*m;
    float scale = gamma[j] * rsqrtf(var + BN_EPS);
    sc[j] = scale;
    sh[j] = beta[j] - m * scale;
    __syncthreads();
    float b = 0.f;
    for (int k = 0; k < FD; k++) {
        float w = W[k*FD + j];
        g_Wf[k*FD + j] = sc[k] * w;
        b += sh[k] * w;
    }
    g_bf[j] = b;
}

// -------- tensor-core GEMM (bf16x3 split): C = A @ g_Wf + g_bf (opt relu) --
// CTA: 256 threads = 8 warps = 4 m-tiles(16 rows) x 2 n-halves(64 cols).
// smem: As hi/lo [64][68] u32 (bf16 pairs along k), Bs hi/lo [64][136] u32.
#define AS_STRIDE 68
#define BS_STRIDE 136
#define GEMM_SMEM ((2*64*AS_STRIDE + 2*64*BS_STRIDE)*4)

__global__ void gemm128_mma(const float* __restrict__ A, float* __restrict__ C,
                            int M, int relu) {
    extern __shared__ unsigned smu[];
    unsigned* As_hi = smu;
    unsigned* As_lo = As_hi + 64*AS_STRIDE;
    unsigned* Bs_hi = As_lo + 64*AS_STRIDE;
    unsigned* Bs_lo = Bs_hi + 64*BS_STRIDE;
    int tid = threadIdx.x;
    int row0 = blockIdx.x * 64;

    // stage W: hi/lo bf16 pairs along k (k2 = k/2)
    for (int i = tid; i < 64*128; i += 256) {
        int k2 = i >> 7, n = i & 127;
        float w0 = g_Wf[(2*k2)*FD + n];
        float w1 = g_Wf[(2*k2+1)*FD + n];
        unsigned hp = pack_bf16x2(w0, w1);
        float r0 = w0 - bf16lo_f(hp);
        float r1 = w1 - bf16hi_f(hp);
        Bs_hi[k2*BS_STRIDE + n] = hp;
        Bs_lo[k2*BS_STRIDE + n] = pack_bf16x2(r0, r1);
    }
    // stage A tile (64 rows), hi/lo bf16 pairs along k
    for (int i = tid; i < 64*64; i += 256) {
        int r = i >> 6, c2 = i & 63;
        float2 a = make_float2(0.f, 0.f);
        if (row0 + r < M) a = ((const float2*)A)[(size_t)(row0 + r)*64 + c2];
        unsigned hp = pack_bf16x2(a.x, a.y);
        float r0 = a.x - bf16lo_f(hp);
        float r1 = a.y - bf16hi_f(hp);
        As_hi[r*AS_STRIDE + c2] = hp;
        As_lo[r*AS_STRIDE + c2] = pack_bf16x2(r0, r1);
    }
    __syncthreads();

    int wid = tid >> 5, lane = tid & 31;
    int g = lane >> 2, t = lane & 3;
    int mw = wid & 3, nh = wid >> 2;
    int ra = (mw*16 + g)*AS_STRIDE;
    int rb = ra + 8*AS_STRIDE;

    float c[8][4];
    #pragma unroll
    for (int i = 0; i < 8; i++) { c[i][0]=0.f; c[i][1]=0.f; c[i][2]=0.f; c[i][3]=0.f; }

    #pragma unroll
    for (int kk = 0; kk < 8; kk++) {
        int ca = kk*8 + t;
        unsigned ah0 = As_hi[ra + ca],     ah1 = As_hi[rb + ca];
        unsigned ah2 = As_hi[ra + ca + 4], ah3 = As_hi[rb + ca + 4];
        unsigned al0 = As_lo[ra + ca],     al1 = As_lo[rb + ca];
        unsigned al2 = As_lo[ra + ca + 4], al3 = As_lo[rb + ca + 4];
        int kb0 = (kk*8 + t)*BS_STRIDE + nh*64;
        int kb1 = kb0 + 4*BS_STRIDE;
        #pragma unroll
        for (int nt = 0; nt < 8; nt++) {
            int n = nt*8 + g;
            unsigned bh0 = Bs_hi[kb0 + n], bh1 = Bs_hi[kb1 + n];
            unsigned bl0 = Bs_lo[kb0 + n], bl1 = Bs_lo[kb1 + n];
            MMA_BF16(c[nt], ah0, ah1, ah2, ah3, bh0, bh1);
            MMA_BF16(c[nt], ah0, ah1, ah2, ah3, bl0, bl1);
            MMA_BF16(c[nt], al0, al1, al2, al3, bh0, bh1);
        }
    }

    // epilogue: D[g][2t,2t+1] = c0,c1 ; D[g+8][2t,2t+1] = c2,c3
    #pragma unroll
    for (int nt = 0; nt < 8; nt++) {
        int col = nh*64 + nt*8 + 2*t;
        float b0 = g_bf[col], b1 = g_bf[col+1];
        int r = row0 + mw*16 + g;
        float v0 = c[nt][0] + b0, v1 = c[nt][1] + b1;
        float v2 = c[nt][2] + b0, v3 = c[nt][3] + b1;
        if (relu) {
            v0 = fmaxf(v0, 0.f); v1 = fmaxf(v1, 0.f);
            v2 = fmaxf(v2, 0.f); v3 = fmaxf(v3, 0.f);
        }
        if (r < M)     ((float2*)C)[((size_t)r*FD + col) >> 1]     = make_float2(v0, v1);
        if (r + 8 < M) ((float2*)C)[((size_t)(r+8)*FD + col) >> 1] = make_float2(v2, v3);
    }
}

// ---------------- per-node attention coefficients -----------
__global__ void node_al(const float* __restrict__ asrc, const float* __restrict__ adst) {
    int lane = threadIdx.x & 31;
    int warp = (blockIdx.x*blockDim.x + threadIdx.x) >> 5;
    int nwarps = (gridDim.x*blockDim.x) >> 5;
    int head = lane >> 3, dq = lane & 7;
    float4 as4 = ((const float4*)asrc)[head*8 + dq];
    float4 ad4 = ((const float4*)adst)[head*8 + dq];
    for (int n = warp; n < NN; n += nwarps) {
        float4 v = ((const float4*)g_h2)[n*32 + lane];
        float ps = v.x*as4.x + v.y*as4.y + v.z*as4.z + v.w*as4.w;
        float pd = v.x*ad4.x + v.y*ad4.y + v.z*ad4.z + v.w*ad4.w;
        #pragma unroll
        for (int off = 4; off; off >>= 1) {
            ps += __shfl_down_sync(0xffffffffu, ps, off, 8);
            pd += __shfl_down_sync(0xffffffffu, pd, off, 8);
        }
        if (dq == 0) {
            g_als[n*4 + head] = ps;
            g_ald[n*4 + head] = pd;
        }
    }
}

// ------ fused GAT aggregation: warp per node, online softmax, 2 passes ----
__global__ void gat_gather(const float* __restrict__ bias) {
    int warp = (blockIdx.x*blockDim.x + threadIdx.x) >> 5;
    if (warp >= NN) return;
    int lane = threadIdx.x & 31;
    int n = warp;
    int rs = g_off[n], re = g_off[n+1];

    float4 aldv = ((const float4*)g_ald)[n];

    // pass A: per-head online (max, sum) — lane-parallel over edges
    const float MINIT = -1e30f;   // finite: avoids inf-inf NaN on empty lanes
    float m0=MINIT, m1=MINIT, m2=MINIT, m3=MINIT;
    float s0=0.f, s1=0.f, s2=0.f, s3=0.f;
    for (int e = rs + lane; e < re; e += 32) {
        int s = g_csrc[e];
        float4 a = ((const float4*)g_als)[s];
        float l0 = a.x + aldv.x; l0 = (l0 > 0.f) ? l0 : NEG*l0;
        float l1 = a.y + aldv.y; l1 = (l1 > 0.f) ? l1 : NEG*l1;
        float l2 = a.z + aldv.z; l2 = (l2 > 0.f) ? l2 : NEG*l2;
        float l3 = a.w + aldv.w; l3 = (l3 > 0.f) ? l3 : NEG*l3;
        float nm;
        nm = fmaxf(m0, l0); s0 = s0*__expf(m0-nm) + __expf(l0-nm); m0 = nm;
        nm = fmaxf(m1, l1); s1 = s1*__expf(m1-nm) + __expf(l1-nm); m1 = nm;
        nm = fmaxf(m2, l2); s2 = s2*__expf(m2-nm) + __expf(l2-nm); m2 = nm;
        nm = fmaxf(m3, l3); s3 = s3*__expf(m3-nm) + __expf(l3-nm); m3 = nm;
    }
    #pragma unroll
    for (int off = 16; off; off >>= 1) {
        float om, os, nm;
        om = __shfl_xor_sync(0xffffffffu, m0, off); os = __shfl_xor_sync(0xffffffffu, s0, off);
        nm = fmaxf(m0, om); s0 = s0*__expf(m0-nm) + os*__expf(om-nm); m0 = nm;
        om = __shfl_xor_sync(0xffffffffu, m1, off); os = __shfl_xor_sync(0xffffffffu, s1, off);
        nm = fmaxf(m1, om); s1 = s1*__expf(m1-nm) + os*__expf(om-nm); m1 = nm;
        om = __shfl_xor_sync(0xffffffffu, m2, off); os = __shfl_xor_sync(0xffffffffu, s2, off);
        nm = fmaxf(m2, om); s2 = s2*__expf(m2-nm) + os*__expf(om-nm); m2 = nm;
        om = __shfl_xor_sync(0xffffffffu, m3, off); os = __shfl_xor_sync(0xffffffffu, s3, off);
        nm = fmaxf(m3, om); s3 = s3*__expf(m3-nm) + os*__expf(om-nm); m3 = nm;
    }

    int head = lane >> 3;
    float mh   = (head < 2) ? (head ? m1 : m0) : ((head == 2) ? m2 : m3);
    float sh   = (head < 2) ? (head ? s1 : s0) : ((head == 2) ? s2 : s3);
    float alD  = (head < 2) ? (head ? aldv.y : aldv.x) : ((head == 2) ? aldv.z : aldv.w);
    float invh = 1.f / (sh + 1e-16f);

    // pass B: weighted gather-accumulate (dim-parallel, sequential over edges)
    float4 acc = make_float4(0.f, 0.f, 0.f, 0.f);
    int e = rs;
    int s_cur = (e < re) ? g_csrc[e] : 0;
    for (; e < re; e++) {
        int s = s_cur;
        if (e + 1 < re) s_cur = g_csrc[e+1];
        float4 a = ((const float4*)g_als)[s];     // broadcast (same addr all lanes)
        float alS = (head < 2) ? (head ? a.y : a.x) : ((head == 2) ? a.z : a.w);
        float l = alS + alD; l = (l > 0.f) ? l : NEG*l;
        float w = __expf(l - mh) * invh;
        float4 v = ((const float4*)g_h2)[s*32 + lane];
        acc.x += v.x*w; acc.y += v.y*w;
        acc.z += v.z*w; acc.w += v.w*w;
    }

    float4 b4 = ((const float4*)bias)[lane];
    acc.x = fmaxf(acc.x + b4.x, 0.f); acc.y = fmaxf(acc.y + b4.y, 0.f);
    acc.z = fmaxf(acc.z + b4.z, 0.f); acc.w = fmaxf(acc.w + b4.w, 0.f);
    ((float4*)g_h)[n*32 + lane] = acc;
}

// ---------------- pooling + head ----------------
__global__ void zero_pool() {
    int t = blockIdx.x*blockDim.x + threadIdx.x;
    if (t < NG*FD) g_pool[t] = 0.f;
}

__global__ void pool_kernel(const int* __restrict__ batch) {
    int t = blockIdx.x*blockDim.x + threadIdx.x;
    if (t >= NN*32) return;
    int node = t >> 5, q = t & 31;
    int b = batch[node];
    float4 v = ((const float4*)g_h)[t];
    red_add_v4(&g_pool[b*FD + q*4], v);
}

__global__ void small_bn(int sel, const float* __restrict__ gamma,
                         const float* __restrict__ beta) {
    const float* X = sel ? g_g2 : g_pool;
    float* sc = sel ? g_sc2 : g_sc1;
    float* sh = sel ? g_sh2 : g_sh1;
    int j = threadIdx.x;
    float s = 0.f, q = 0.f;
    for (int r = 0; r < NG; r++) { float v = X[r*FD + j]; s += v; q += v*v; }
    float m = s * (1.f/NG);
    float var = q * (1.f/NG) - m*m;
    float scale = gamma[j] * rsqrtf(var + BN_EPS);
    sc[j] = scale; sh[j] = beta[j] - m*scale;
}

__global__ void small_linear(const float* __restrict__ W, const float* __restrict__ b) {
    __shared__ float row[FD];
    int r = blockIdx.x, j = threadIdx.x;
    row[j] = g_pool[r*FD + j] * g_sc1[j] + g_sh1[j];
    __syncthreads();
    float acc = b[j];
    #pragma unroll 8
    for (int k = 0; k < FD; k++) acc += row[k] * W[k*FD + j];
    g_g2[r*FD + j] = fmaxf(acc, 0.f);
}

__global__ void classifier(const float* __restrict__ W, const float* __restrict__ b,
                           float* __restrict__ out) {
    __shared__ float row[FD];
    __shared__ float z[16];
    __shared__ float red2[2];
    int r = blockIdx.x, t = threadIdx.x;
    for (int i = t; i < FD; i += 32) row[i] = g_g2[r*FD + i] * g_sc2[i] + g_sh2[i];
    __syncthreads();
    if (t < 10) {
        float acc = b[t];
        for (int k = 0; k < FD; k++) acc += row[k] * W[k*10 + t];
        z[t] = acc;
    }
    __syncthreads();
    if (t == 0) {
        float m = z[0];
        for (int i = 1; i < 10; i++) m = fmaxf(m, z[i]);
        float s = 0.f;
        for (int i = 0; i < 10; i++) s += expf(z[i] - m);
        red2[0] = m; red2[1] = logf(s);
    }
    __syncthreads();
    if (t < 10) out[r*10 + t] = z[t] - red2[0] - red2[1];
}

// ---------------- launch ----------------
extern "C" void kernel_launch(void* const* d_in, const int* in_sizes, int n_in,
                              void* d_out, int out_size) {
    const float* x        = (const float*)d_in[0];
    const int*   eidx     = (const int*)  d_in[1];
    const int*   batch    = (const int*)  d_in[2];
    const float* w_feat   = (const float*)d_in[3];
    const float* bnf_g    = (const float*)d_in[4];
    const float* bnf_b    = (const float*)d_in[5];
    const float* bnc_g    = (const float*)d_in[6];
    const float* bnc_b    = (const float*)d_in[7];
    const float* gat_w    = (const float*)d_in[8];
    const float* gat_asrc = (const float*)d_in[9];
    const float* gat_adst = (const float*)d_in[10];
    const float* gat_b    = (const float*)d_in[11];
    const float* bnfc_g   = (const float*)d_in[12];
    const float* bnfc_b   = (const float*)d_in[13];
    const float* lin_w    = (const float*)d_in[14];
    const float* lin_b    = (const float*)d_in[15];
    const float* bnh_g    = (const float*)d_in[16];
    const float* bnh_b    = (const float*)d_in[17];
    const float* cls_w    = (const float*)d_in[18];
    const float* cls_b    = (const float*)d_in[19];
    float* out = (float*)d_out;

    const int* src = eidx;
    const int* dst = eidx + NE;

    float *p_h, *p_h2;
    cudaGetSymbolAddress((void**)&p_h,  g_h);
    cudaGetSymbolAddress((void**)&p_h2, g_h2);

    cudaFuncSetAttribute(gemm128_mma, cudaFuncAttributeMaxDynamicSharedMemorySize, GEMM_SMEM);
    const int GEMM_GRID = (NN + 63) / 64;

    // ---- CSR build (reused by all 3 convs) ----
    zero_deg<<<(NN+255)/256, 256>>>();
    count_deg<<<(ET+255)/256, 256>>>(dst);
    scan_deg<<<1, 1024>>>();
    scatter_csr<<<(ET+255)/256, 256>>>(src, dst);

    // ---- bn_feat fold + gfn GCN + relu ----
    zero_stat<<<1, 256>>>();
    bn_stats<<<512, FD>>>(x, NN);
    fold<<<1, FD>>>(w_feat, bnf_g, bnf_b, 1.f/NN);
    gemm128_mma<<<GEMM_GRID, 256, GEMM_SMEM>>>(x, p_h, NN, 1);

    // ---- 3 x (BN + GATConv + relu) ----
    for (int i = 0; i < 3; i++) {
        zero_stat<<<1, 256>>>();
        bn_stats<<<512, FD>>>(p_h, NN);
        fold<<<1, FD>>>(gat_w + i*FD*FD, bnc_g + i*FD, bnc_b + i*FD, 1.f/NN);
        gemm128_mma<<<GEMM_GRID, 256, GEMM_SMEM>>>(p_h, p_h2, NN, 0);
        node_al<<<1024, 256>>>(gat_asrc + i*FD, gat_adst + i*FD);
        gat_gather<<<(NN*32+255)/256, 256>>>(gat_b + i*FD);
    }

    // ---- pool + head ----
    zero_pool<<<128, 256>>>();
    pool_kernel<<<NN*32/256, 256>>>(batch);
    small_bn<<<1, FD>>>(0, bnfc_g, bnfc_b);
    small_linear<<<NG, FD>>>(lin_w, lin_b);
    small_bn<<<1, FD>>>(1, bnh_g, bnh_b);
    classifier<<<NG, 32>>>(cls_w, cls_b, out);
}